// round 14
// baseline (speedup 1.0000x reference)
#include <cuda_runtime.h>
#include <cuda_bf16.h>
#include <math.h>
#include <stdint.h>

typedef __nv_bfloat16 bf16;
typedef unsigned long long ull;

#define SQ 2048
#define DM 2048
#define NH 16
#define NKV 8
#define HD 128
#define KN (NKV*HD)          // 1024
#define TOPK 40
#define SCALE 0.08838834764831845f  // 128^-0.5

#define K3P (3*DM)           // 6144: triple-K (V, O projections)

// ---------------- scratch (device globals; no allocations allowed) ----------
__device__ float g_xT [(size_t)DM * SQ];          // x transposed   [k][m]
__device__ float g_wqT[(size_t)DM * DM];          // Wq transposed  [k][n]
__device__ float g_wkT[(size_t)DM * KN];          // Wk transposed  [k][n]
__device__ float g_qp [(size_t)2 * SQ * DM];      // Q projection K-split partials
__device__ float g_kp [(size_t)2 * SQ * KN];      // K projection K-split partials
__device__ float g_v  [(size_t)SQ * KN];
__device__ float g_qr [(size_t)NH  * SQ * HD];
__device__ float g_kr [(size_t)NKV * SQ * HD];
__device__ bf16  g_scb[(size_t)NH * SQ * SQ];     // screening scores, bf16 (128 MB)
__device__ bf16  g_x3 [(size_t)SQ * K3P];
__device__ bf16  g_wv3[(size_t)KN * K3P];
__device__ bf16  g_wo3[(size_t)DM * K3P];
__device__ bf16  g_qr1[(size_t)NH  * SQ * HD];
__device__ bf16  g_kr1[(size_t)NKV * SQ * HD];
__device__ bf16  g_at3[(size_t)SQ * K3P];

// ================= packed fp32x2 helpers (sm_100+ base ISA) =================
__device__ __forceinline__ ull pack2(float x, float y) {
    ull r;
    asm("mov.b64 %0, {%1,%2};" : "=l"(r) : "f"(x), "f"(y));
    return r;
}
__device__ __forceinline__ void unpack2(ull v, float& x, float& y) {
    asm("mov.b64 {%0,%1}, %2;" : "=f"(x), "=f"(y) : "l"(v));
}
__device__ __forceinline__ void ffma2(ull& d, ull a, ull b) {
    asm("fma.rn.f32x2 %0, %1, %2, %3;" : "=l"(d) : "l"(a), "l"(b), "l"(d));
}
__device__ __forceinline__ uint32_t smem_u32(const void* p) {
    uint32_t a;
    asm("{ .reg .u64 t; cvta.to.shared.u64 t, %1; cvt.u32.u64 %0, t; }" : "=r"(a) : "l"(p));
    return a;
}

// ================= 32x32 tiled transpose: src[R][C] -> dst[C][R] ============
__global__ void transpose_kernel(const float* __restrict__ src,
                                 float* __restrict__ dst, int R, int C)
{
    __shared__ float tile[32][33];
    int bx = blockIdx.x * 32, by = blockIdx.y * 32;
    int tx = threadIdx.x, ty = threadIdx.y;
#pragma unroll
    for (int j = 0; j < 32; j += 8)
        tile[ty + j][tx] = src[(size_t)(by + ty + j) * C + bx + tx];
    __syncthreads();
#pragma unroll
    for (int j = 0; j < 32; j += 8)
        dst[(size_t)(bx + ty + j) * R + by + tx] = tile[tx][ty + j];
}

// ============ fused Q+K fp32 projection, cp.async 3-stage, 16x8 tile ========
// grid (24, 8, 2): x<16 -> Q tile, else K tile; z = K half. Block tile 256x128.
// Inputs are k-major transposed buffers; tiles land in [kk][row] layout via
// contiguous cp.async. Per-element FMA chain ascends k exactly as rounds 9-12
// -> g_q/g_k bit-identical.
#define QK_STAGES 3
#define QK_A_BYTES 16384u           // 16 kk x 256 m x 4B
#define QK_B_BYTES 8192u            // 16 kk x 128 n x 4B
#define QK_STAGE_BYTES (QK_A_BYTES + QK_B_BYTES)   // 24576
#define QK_SMEM (QK_STAGES * 24576)                // 73728

__device__ __forceinline__ void qk_cp_tile(uint32_t smA, uint32_t smB,
                                           const float* __restrict__ At, long mcol0,
                                           const float* __restrict__ Bt, long ncol0,
                                           int k0, int ldA, int ldB, int tid) {
    // A: 16 kk-rows x 1024 bytes, 1024 transfers of 16B
#pragma unroll
    for (int it = 0; it < 4; it++) {
        int idx = tid + it * 256;          // 0..1023
        int kk  = idx >> 6;                // 0..15
        int c16 = (idx & 63) * 16;         // byte offset in row
        const void* ga = (const char*)(At + (long)(k0 + kk) * ldA + mcol0) + c16;
        asm volatile("cp.async.cg.shared.global [%0], [%1], 16;"
                     :: "r"(smA + (uint32_t)(kk * 1024 + c16)), "l"(ga));
    }
    // B: 16 kk-rows x 512 bytes, 512 transfers of 16B
#pragma unroll
    for (int it = 0; it < 2; it++) {
        int idx = tid + it * 256;          // 0..511
        int kk  = idx >> 5;                // 0..15
        int c16 = (idx & 31) * 16;
        const void* gb = (const char*)(Bt + (long)(k0 + kk) * ldB + ncol0) + c16;
        asm volatile("cp.async.cg.shared.global [%0], [%1], 16;"
                     :: "r"(smB + (uint32_t)(kk * 512 + c16)), "l"(gb));
    }
}

__global__ __launch_bounds__(256, 1) void qk_gemm()
{
    extern __shared__ char smraw[];
    uint32_t base = smem_u32(smraw);
    float* smf = (float*)smraw;

    int bx = blockIdx.x;
    bool isQ = bx < 16;
    long bcol = (long)(isQ ? bx : bx - 16) * 128;
    const float* Bt = isQ ? g_wqT : g_wkT;
    int ldB = isQ ? DM : KN;
    int N   = ldB;
    float* C = isQ ? (g_qp + (size_t)blockIdx.z * SQ * DM)
                   : (g_kp + (size_t)blockIdx.z * SQ * KN);
    long brow = (long)blockIdx.y * 256;
    int kbeg = blockIdx.z * 1024;

    int tid = threadIdx.x;
    int ty  = tid >> 4;      // 0..15 -> 16 M-rows each
    int tx  = tid & 15;      // 0..15 ->  8 N-cols each

    ull acc2[16][4];
#pragma unroll
    for (int i = 0; i < 16; i++)
#pragma unroll
        for (int j = 0; j < 4; j++) acc2[i][j] = pack2(0.f, 0.f);

    const int NC = 64;   // 1024 / 16

    // prologue: prefetch 2 chunks
#pragma unroll
    for (int s = 0; s < 2; s++) {
        uint32_t st = base + (uint32_t)s * QK_STAGE_BYTES;
        qk_cp_tile(st, st + QK_A_BYTES, g_xT, brow, Bt, bcol,
                   kbeg + s * 16, SQ, ldB, tid);
        asm volatile("cp.async.commit_group;" ::: "memory");
    }

    for (int c = 0; c < NC; c++) {
        if (c + 1 < NC) asm volatile("cp.async.wait_group 1;" ::: "memory");
        else            asm volatile("cp.async.wait_group 0;" ::: "memory");
        __syncthreads();

        if (c + 2 < NC) {
            uint32_t st = base + (uint32_t)((c + 2) % QK_STAGES) * QK_STAGE_BYTES;
            qk_cp_tile(st, st + QK_A_BYTES, g_xT, brow, Bt, bcol,
                       kbeg + (c + 2) * 16, SQ, ldB, tid);
            asm volatile("cp.async.commit_group;" ::: "memory");
        }

        const float* As = smf + ((c % QK_STAGES) * QK_STAGE_BYTES) / 4;          // [kk][256]
        const float* Bs = As + QK_A_BYTES / 4;                                   // [kk][128]

#pragma unroll
        for (int kk = 0; kk < 16; kk++) {
            const ull* bp = (const ull*)&Bs[kk * 128 + tx * 8];
            ull bb0 = bp[0], bb1 = bp[1], bb2 = bp[2], bb3 = bp[3];
            float av[16];
            *(float4*)&av[0]  = *(const float4*)&As[kk * 256 + ty * 16];
            *(float4*)&av[4]  = *(const float4*)&As[kk * 256 + ty * 16 + 4];
            *(float4*)&av[8]  = *(const float4*)&As[kk * 256 + ty * 16 + 8];
            *(float4*)&av[12] = *(const float4*)&As[kk * 256 + ty * 16 + 12];
#pragma unroll
            for (int i = 0; i < 16; i++) {
                ull a2 = pack2(av[i], av[i]);
                ffma2(acc2[i][0], a2, bb0);
                ffma2(acc2[i][1], a2, bb1);
                ffma2(acc2[i][2], a2, bb2);
                ffma2(acc2[i][3], a2, bb3);
            }
        }
        __syncthreads();
    }

#pragma unroll
    for (int i = 0; i < 16; i++) {
        long rr = brow + ty * 16 + i;
        float o[8];
#pragma unroll
        for (int j = 0; j < 4; j++) unpack2(acc2[i][j], o[2 * j], o[2 * j + 1]);
#pragma unroll
        for (int j = 0; j < 8; j++)
            C[rr * N + bcol + tx * 8 + j] = o[j];
    }
}

// ================= HMMA helpers =============================================
__device__ __forceinline__ void ldmatrix_x4(uint32_t* r, uint32_t addr) {
    asm volatile("ldmatrix.sync.aligned.m8n8.x4.shared.b16 {%0,%1,%2,%3}, [%4];"
        : "=r"(r[0]), "=r"(r[1]), "=r"(r[2]), "=r"(r[3]) : "r"(addr));
}
__device__ __forceinline__ void mma16816(float* c, const uint32_t* a, const uint32_t* b) {
    asm volatile(
        "mma.sync.aligned.m16n8k16.row.col.f32.bf16.bf16.f32 "
        "{%0,%1,%2,%3}, {%4,%5,%6,%7}, {%8,%9}, {%0,%1,%2,%3};"
        : "+f"(c[0]), "+f"(c[1]), "+f"(c[2]), "+f"(c[3])
        : "r"(a[0]), "r"(a[1]), "r"(a[2]), "r"(a[3]), "r"(b[0]), "r"(b[1]));
}
__device__ __forceinline__ uint32_t sw128(uint32_t bo) { return bo ^ ((bo >> 3) & 0x70); }

// ============ bf16 GEMM-NT with cp.async 3-stage pipeline (HMMA) ============
#define STAGES 3
#define STAGE_BYTES 32768u
#define GEMM3_SMEM (STAGES * 32768 + 256)

__device__ __forceinline__ void cp_tile(uint32_t smA, uint32_t smB,
                                        const bf16* __restrict__ A, long rowA,
                                        const bf16* __restrict__ B, long rowB,
                                        int k0, int ld, int tid) {
#pragma unroll
    for (int it = 0; it < 4; it++) {
        int idx = tid + it * 256;
        int rr  = idx >> 3;
        int c16 = (idx & 7) * 16;
        uint32_t sw = sw128((uint32_t)(rr * 128 + c16));
        const void* ga = (const char*)(A + (rowA + rr) * (long)ld + k0) + c16;
        const void* gb = (const char*)(B + (rowB + rr) * (long)ld + k0) + c16;
        asm volatile("cp.async.cg.shared.global [%0], [%1], 16;" :: "r"(smA + sw), "l"(ga));
        asm volatile("cp.async.cg.shared.global [%0], [%1], 16;" :: "r"(smB + sw), "l"(gb));
    }
}

// shared mainloop; BFOUT=0 -> fp32 C, BFOUT=1 -> bf16 C
template <int BFOUT>
__device__ __forceinline__ void gemm3_body(
    const bf16* __restrict__ Az, const bf16* __restrict__ Bz,
    float* Cz, bf16* Czb, int N, int K, float alpha)
{
    extern __shared__ char smraw[];
    uint32_t raw  = smem_u32(smraw);
    uint32_t base = (raw + 127u) & ~127u;

    long brow = (long)blockIdx.y * 128;
    long bcol = (long)blockIdx.x * 128;
    int tid  = threadIdx.x;
    int lane = tid & 31;
    int wid  = tid >> 5;
    int wm   = wid & 3;
    int wn   = wid >> 2;

    float acc[2][8][4];
#pragma unroll
    for (int i = 0; i < 2; i++)
#pragma unroll
        for (int j = 0; j < 8; j++)
#pragma unroll
            for (int q = 0; q < 4; q++) acc[i][j][q] = 0.f;

    int NC = K / 64;
    {
        int npre = NC < 2 ? NC : 2;
        for (int s = 0; s < npre; s++) {
            uint32_t st = base + (uint32_t)s * STAGE_BYTES;
            cp_tile(st, st + 16384u, Az, brow, Bz, bcol, s * 64, K, tid);
            asm volatile("cp.async.commit_group;" ::: "memory");
        }
    }

    int aRow = wm * 32 + (lane & 15);
    int aCol = (lane >> 4) * 16;
    int bRow = wn * 64 + ((lane >> 4) << 3) + (lane & 7);
    int bCol = ((lane >> 3) & 1) * 16;

    for (int c = 0; c < NC; c++) {
        if (c + 1 < NC) asm volatile("cp.async.wait_group 1;" ::: "memory");
        else            asm volatile("cp.async.wait_group 0;" ::: "memory");
        __syncthreads();

        if (c + 2 < NC) {
            uint32_t st = base + (uint32_t)((c + 2) % STAGES) * STAGE_BYTES;
            cp_tile(st, st + 16384u, Az, brow, Bz, bcol, (c + 2) * 64, K, tid);
            asm volatile("cp.async.commit_group;" ::: "memory");
        }

        uint32_t smA = base + (uint32_t)(c % STAGES) * STAGE_BYTES;
        uint32_t smB = smA + 16384u;

#pragma unroll
        for (int ks = 0; ks < 4; ks++) {
            uint32_t a[2][4];
#pragma unroll
            for (int mt = 0; mt < 2; mt++) {
                uint32_t bo = (uint32_t)((aRow + mt * 16) * 128 + aCol + ks * 32);
                ldmatrix_x4(a[mt], smA + sw128(bo));
            }
            uint32_t bb[4][4];
#pragma unroll
            for (int p = 0; p < 4; p++) {
                uint32_t bo = (uint32_t)((bRow + p * 16) * 128 + bCol + ks * 32);
                ldmatrix_x4(bb[p], smB + sw128(bo));
            }
#pragma unroll
            for (int mt = 0; mt < 2; mt++)
#pragma unroll
                for (int nt = 0; nt < 8; nt++)
                    mma16816(acc[mt][nt], a[mt], &bb[nt >> 1][(nt & 1) * 2]);
        }
        __syncthreads();
    }

    long r0 = brow + wm * 32 + (lane >> 2);
    long c0 = bcol + wn * 64 + (lane & 3) * 2;
#pragma unroll
    for (int mt = 0; mt < 2; mt++) {
#pragma unroll
        for (int nt = 0; nt < 8; nt++) {
            long rr = r0 + mt * 16;
            long cc = c0 + nt * 8;
            if (BFOUT) {
                __nv_bfloat162 v0 = __floats2bfloat162_rn(alpha * acc[mt][nt][0], alpha * acc[mt][nt][1]);
                __nv_bfloat162 v1 = __floats2bfloat162_rn(alpha * acc[mt][nt][2], alpha * acc[mt][nt][3]);
                *(__nv_bfloat162*)(Czb + rr * N + cc)       = v0;
                *(__nv_bfloat162*)(Czb + (rr + 8) * N + cc) = v1;
            } else {
                float2 v0 = make_float2(alpha * acc[mt][nt][0], alpha * acc[mt][nt][1]);
                float2 v1 = make_float2(alpha * acc[mt][nt][2], alpha * acc[mt][nt][3]);
                *(float2*)(Cz + rr * N + cc)       = v0;
                *(float2*)(Cz + (rr + 8) * N + cc) = v1;
            }
        }
    }
}

__global__ __launch_bounds__(256, 1) void gemm3_cp(
    const bf16* __restrict__ A, const bf16* __restrict__ B, float* __restrict__ C,
    int N, int K, long sA, long sB, long sC, float alpha, int bDiv)
{
    const bf16* Az = A + (long)blockIdx.z * sA;
    const bf16* Bz = B + (long)(blockIdx.z / bDiv) * sB;
    float*      Cz = C + (long)blockIdx.z * sC;
    gemm3_body<0>(Az, Bz, Cz, nullptr, N, K, alpha);
}

__global__ __launch_bounds__(256, 1) void gemm3_cp_bf(
    const bf16* __restrict__ A, const bf16* __restrict__ B, bf16* __restrict__ C,
    int N, int K, long sA, long sB, long sC, float alpha, int bDiv)
{
    const bf16* Az = A + (long)blockIdx.z * sA;
    const bf16* Bz = B + (long)(blockIdx.z / bDiv) * sB;
    bf16*       Cz = C + (long)blockIdx.z * sC;
    gemm3_body<1>(Az, Bz, nullptr, Cz, N, K, alpha);
}

// ================= fp32 -> bf16x3 limb conversion ===========================
// A-type row: [h1 | h1 | h2]    B-type row: [h1 | h2 | h1]
__global__ void conv3_kernel(const float4* __restrict__ src, bf16* __restrict__ dst,
                             long n4, int Kq, int isA)
{
    long i = (long)blockIdx.x * blockDim.x + threadIdx.x;
    if (i >= n4) return;
    long r  = i / Kq;
    int  c4 = (int)(i - r * Kq) * 4;
    int  K  = Kq * 4;
    float4 f = src[i];
    union { bf16 h[4]; uint2 u; } H1, H2;
    float fa[4] = {f.x, f.y, f.z, f.w};
#pragma unroll
    for (int j = 0; j < 4; j++) {
        H1.h[j] = __float2bfloat16(fa[j]);
        H2.h[j] = __float2bfloat16(fa[j] - __bfloat162float(H1.h[j]));
    }
    bf16* d = dst + r * (long)(3 * K) + c4;
    *(uint2*)(d)         = H1.u;
    *(uint2*)(d + K)     = isA ? H1.u : H2.u;
    *(uint2*)(d + 2 * K) = isA ? H2.u : H1.u;
}

// ================= rms-norm + rope (fused partial-halves add) ===============
__device__ __forceinline__ float blockSum128(float v, float* red) {
#pragma unroll
    for (int o = 16; o > 0; o >>= 1) v += __shfl_down_sync(0xffffffffu, v, o);
    if ((threadIdx.x & 31) == 0) red[threadIdx.x >> 5] = v;
    __syncthreads();
    return red[0] + red[1] + red[2] + red[3];
}

__global__ void rope_q_kernel(const float* __restrict__ cosb,
                              const float* __restrict__ sinb,
                              const float* __restrict__ w)
{
    int s = blockIdx.x, h = blockIdx.y, d = threadIdx.x;
    __shared__ float red[4];
    __shared__ float sh[HD];
    size_t off = (size_t)s * DM + h * HD + d;
    float v = g_qp[off] + g_qp[(size_t)SQ * DM + off];   // half0 + half1
    float ss = blockSum128(v * v, red);
    float inv = rsqrtf(ss * (1.0f / HD) + 1e-6f);
    float qn = v * inv * w[d];
    sh[d] = qn;
    __syncthreads();
    float rot = (d < 64) ? -sh[d + 64] : sh[d - 64];
    float f = qn * cosb[s * HD + d] + rot * sinb[s * HD + d];
    g_qr [((size_t)h * SQ + s) * HD + d] = f;
    g_qr1[((size_t)h * SQ + s) * HD + d] = __float2bfloat16(f);
}

__global__ void rope_k_kernel(const float* __restrict__ cosb,
                              const float* __restrict__ sinb,
                              const float* __restrict__ w)
{
    int s = blockIdx.x, h = blockIdx.y, d = threadIdx.x;
    __shared__ float red[4];
    __shared__ float sh[HD];
    size_t off = (size_t)s * KN + h * HD + d;
    float v = g_kp[off] + g_kp[(size_t)SQ * KN + off];   // half0 + half1
    float ss = blockSum128(v * v, red);
    float inv = rsqrtf(ss * (1.0f / HD) + 1e-6f);
    float kn = v * inv * w[d];
    sh[d] = kn;
    __syncthreads();
    float rot = (d < 64) ? -sh[d + 64] : sh[d - 64];
    float f = kn * cosb[s * HD + d] + rot * sinb[s * HD + d];
    g_kr [((size_t)h * SQ + s) * HD + d] = f;
    g_kr1[((size_t)h * SQ + s) * HD + d] = __float2bfloat16(f);
}

// ================= screening + exact rescore + softmax + sparse PV ==========
__device__ __forceinline__ unsigned fkey(float f) {
    unsigned u = __float_as_uint(f);
    return (u & 0x80000000u) ? ~u : (u | 0x80000000u);
}
__device__ __forceinline__ float unfkey(unsigned u) {
    unsigned v = (u & 0x80000000u) ? (u & 0x7FFFFFFFu) : ~u;
    return __uint_as_float(v);
}

#define CAP 320

__global__ void attn_select_kernel()
{
    int row = blockIdx.x, h = blockIdx.y;
    int kvh = h >> 1;
    int t = threadIdx.x;
    int lane = t & 31;
    int wid  = t >> 5;
    const uint4* srow = (const uint4*)(g_scb + ((size_t)h * SQ + row) * SQ);

    // 16 bf16 scores per thread via 2 x uint4 (8 bf16 each)
    float    val[16];
    unsigned key[16];
#pragma unroll
    for (int i = 0; i < 2; i++) {
        uint4 u = srow[t + i * 128];
        unsigned ws[4] = {u.x, u.y, u.z, u.w};
#pragma unroll
        for (int wq = 0; wq < 4; wq++) {
            float lo = __bfloat162float(__ushort_as_bfloat16((unsigned short)(ws[wq] & 0xFFFFu)));
            float hi = __bfloat162float(__ushort_as_bfloat16((unsigned short)(ws[wq] >> 16)));
            int j = i * 8 + wq * 2;
            val[j] = lo;     key[j]     = fkey(lo);
            val[j + 1] = hi; key[j + 1] = fkey(hi);
        }
    }

    __shared__ float redf[4];
    __shared__ int   redc[2][4];

    // approx threshold key: prefix binary search over top 16 bits only.
    unsigned thrKey = 0u;
#pragma unroll
    for (int b = 31; b >= 16; b--) {
        unsigned cand = thrKey | (1u << b);
        int c = 0;
#pragma unroll
        for (int i = 0; i < 16; i++) c += (key[i] >= cand);
        c = __reduce_add_sync(0xffffffffu, c);
        int buf = b & 1;
        if (lane == 0) redc[buf][wid] = c;
        __syncthreads();
        int cnt = redc[buf][0] + redc[buf][1] + redc[buf][2] + redc[buf][3];
        if (cnt >= TOPK) thrKey = cand;
    }
    // adaptive band: covers bf16 score-storage + screening GEMM error
    float thr  = unfkey(thrKey);
    float band = thr - (0.06f + 0.01f * fabsf(thr));

    // band mask + deterministic compaction; col of val[j] = 8*(t + (j>>3)*128) + (j&7)
    unsigned mask = 0;
#pragma unroll
    for (int i = 0; i < 16; i++) {
        int col = 8 * (t + (i >> 3) * 128) + (i & 7);
        if (val[i] >= band || col == row) mask |= (1u << i);
    }
    int mc = __popc(mask);

    __shared__ int cnts[129];
    cnts[t] = mc;
    __syncthreads();
    if (t == 0) {
        int a = 0;
        for (int x = 0; x < 128; x++) { int c = cnts[x]; cnts[x] = a; a += c; }
        cnts[128] = a;
    }
    __syncthreads();
    int total = cnts[128];
    if (total > CAP) total = CAP;

    __shared__ int    sIdx[CAP];
    __shared__ float  sEx[CAP];
    __shared__ float  sP[CAP];
    __shared__ float4 sQ4[32];
    {
        int p = cnts[t];
#pragma unroll
        for (int i = 0; i < 16; i++) {
            if (mask & (1u << i)) {
                if (p < CAP) sIdx[p] = 8 * (t + (i >> 3) * 128) + (i & 7);
                p++;
            }
        }
    }
    if (t < 32) sQ4[t] = ((const float4*)(g_qr + ((size_t)h * SQ + row) * HD))[t];
    __syncthreads();

    // exact fp32 rescore: one warp per candidate, float4 coalesced loads
    for (int c = wid; c < total; c += 4) {
        const float4* kp = (const float4*)(g_kr + ((size_t)kvh * SQ + sIdx[c]) * HD);
        float4 k4 = kp[lane];
        float4 q4 = sQ4[lane];
        float part = q4.x * k4.x;
        part = fmaf(q4.y, k4.y, part);
        part = fmaf(q4.z, k4.z, part);
        part = fmaf(q4.w, k4.w, part);
#pragma unroll
        for (int o = 16; o > 0; o >>= 1) part += __shfl_down_sync(0xffffffffu, part, o);
        if (lane == 0) sEx[c] = SCALE * part;
    }
    __syncthreads();

    // exact row max over candidates
    float m = -3.4e38f;
    for (int c = t; c < total; c += 128) m = fmaxf(m, sEx[c]);
#pragma unroll
    for (int o = 16; o > 0; o >>= 1) m = fmaxf(m, __shfl_down_sync(0xffffffffu, m, o));
    if (lane == 0) redf[wid] = m;
    __syncthreads();
    float rowmax = fmaxf(fmaxf(redf[0], redf[1]), fmaxf(redf[2], redf[3]));

    // exact top-40 membership among candidates
    for (int c = t; c < total; c += 128) {
        float v = sEx[c];
        int cnt = 0;
        for (int c2 = 0; c2 < total; c2++) cnt += (sEx[c2] > v);
        bool kept = (cnt < TOPK) || (sIdx[c] == row);
        sP[c] = kept ? __expf(v - rowmax) : 0.f;
    }
    __syncthreads();

    // denominator
    float ps = 0.f;
    for (int c = t; c < total; c += 128) ps += sP[c];
#pragma unroll
    for (int o = 16; o > 0; o >>= 1) ps += __shfl_down_sync(0xffffffffu, ps, o);
    if (lane == 0) redf[wid] = ps;
    __syncthreads();
    float denom = redf[0] + redf[1] + redf[2] + redf[3];

    // sparse PV (coalesced v rows)
    float acc = 0.f;
    for (int c = 0; c < total; c++)
        acc += sP[c] * g_v[(size_t)sIdx[c] * KN + kvh * HD + t];

    float o = acc / denom;
    bf16 h1 = __float2bfloat16(o);
    bf16 h2 = __float2bfloat16(o - __bfloat162float(h1));
    bf16* dst = g_at3 + (size_t)row * K3P;
    int col = h * HD + t;
    dst[col] = h1; dst[DM + col] = h1; dst[2 * DM + col] = h2;   // A-type
}

// ================= launch (single stream — linear graph) =====================
extern "C" void kernel_launch(void* const* d_in, const int* in_sizes, int n_in,
                              void* d_out, int out_size)
{
    const float* x    = (const float*)d_in[0];
    const float* cosb = (const float*)d_in[1];
    const float* sinb = (const float*)d_in[2];
    const float* Wq   = (const float*)d_in[3];
    const float* Wk   = (const float*)d_in[4];
    const float* Wv   = (const float*)d_in[5];
    const float* Wo   = (const float*)d_in[6];
    const float* qw   = (const float*)d_in[7];
    const float* kw   = (const float*)d_in[8];
    float* out = (float*)d_out;

    float *pv, *pxT, *pwqT, *pwkT;
    bf16  *pscb, *px3, *pwv3, *pwo3, *pqr1, *pkr1, *pat3;
    cudaGetSymbolAddress((void**)&pv,   g_v);
    cudaGetSymbolAddress((void**)&pxT,  g_xT);
    cudaGetSymbolAddress((void**)&pwqT, g_wqT);
    cudaGetSymbolAddress((void**)&pwkT, g_wkT);
    cudaGetSymbolAddress((void**)&pscb, g_scb);
    cudaGetSymbolAddress((void**)&px3,  g_x3);
    cudaGetSymbolAddress((void**)&pwv3, g_wv3);
    cudaGetSymbolAddress((void**)&pwo3, g_wo3);
    cudaGetSymbolAddress((void**)&pqr1, g_qr1);
    cudaGetSymbolAddress((void**)&pkr1, g_kr1);
    cudaGetSymbolAddress((void**)&pat3, g_at3);

    static bool attr_done = false;
    if (!attr_done) {
        cudaFuncSetAttribute(gemm3_cp,    cudaFuncAttributeMaxDynamicSharedMemorySize, GEMM3_SMEM);
        cudaFuncSetAttribute(gemm3_cp_bf, cudaFuncAttributeMaxDynamicSharedMemorySize, GEMM3_SMEM);
        cudaFuncSetAttribute(qk_gemm,     cudaFuncAttributeMaxDynamicSharedMemorySize, QK_SMEM);
        attr_done = true;
    }

    // transposes for cp.async k-major tiles (x, Wq, Wk)
    transpose_kernel<<<dim3(DM / 32, SQ / 32), dim3(32, 8)>>>(x,  pxT,  SQ, DM);
    transpose_kernel<<<dim3(DM / 32, DM / 32), dim3(32, 8)>>>(Wq, pwqT, DM, DM);
    transpose_kernel<<<dim3(DM / 32, KN / 32), dim3(32, 8)>>>(Wk, pwkT, KN, DM);

    // limb conversions (x, Wv, Wo)
    {
        long n4;
        n4 = (long)SQ * DM / 4;
        conv3_kernel<<<(unsigned)((n4 + 255) / 256), 256>>>((const float4*)x,  px3,  n4, DM / 4, 1);
        n4 = (long)KN * DM / 4;
        conv3_kernel<<<(unsigned)((n4 + 255) / 256), 256>>>((const float4*)Wv, pwv3, n4, DM / 4, 0);
        n4 = (long)DM * DM / 4;
        conv3_kernel<<<(unsigned)((n4 + 255) / 256), 256>>>((const float4*)Wo, pwo3, n4, DM / 4, 0);
    }

    // fused Q+K fp32 projection (cp.async 3-stage, 16x8 tile, K-split x2)
    qk_gemm<<<dim3(24, 8, 2), 256, QK_SMEM>>>();

    // V projection: bf16x3 HMMA
    gemm3_cp<<<dim3(KN / 128, SQ / 128, 1), 256, GEMM3_SMEM>>>(px3, pwv3, pv, KN, K3P, 0, 0, 0, 1.f, 1);

    // rms-norm + rope (fp32 + plain-bf16 screening copies; adds K-split halves)
    rope_q_kernel<<<dim3(SQ, NH),  128>>>(cosb, sinb, qw);
    rope_k_kernel<<<dim3(SQ, NKV), 128>>>(cosb, sinb, kw);

    // screening scores: plain bf16 inputs AND bf16 output buffer
    gemm3_cp_bf<<<dim3(SQ / 128, SQ / 128, NH), 256, GEMM3_SMEM>>>(
        pqr1, pkr1, pscb, SQ, HD,
        (long)SQ * HD, (long)SQ * HD, (long)SQ * SQ, SCALE, 2);

    // screening + exact fp32 rescore + softmax + sparse PV
    attn_select_kernel<<<dim3(SQ, NH), 128>>>();

    // O projection: bf16x3 HMMA
    gemm3_cp<<<dim3(DM / 128, SQ / 128, 1), 256, GEMM3_SMEM>>>(pat3, pwo3, out, DM, K3P, 0, 0, 0, 1.f, 1);
}

// round 15
// speedup vs baseline: 1.0001x; 1.0001x over previous
#include <cuda_runtime.h>
#include <cuda_bf16.h>
#include <math.h>
#include <stdint.h>

typedef __nv_bfloat16 bf16;
typedef unsigned long long ull;

#define SQ 2048
#define DM 2048
#define NH 16
#define NKV 8
#define HD 128
#define KN (NKV*HD)          // 1024
#define TOPK 40
#define SCALE 0.08838834764831845f  // 128^-0.5

#define K3P (3*DM)           // 6144: triple-K (V, O projections)

// ---------------- scratch (device globals; no allocations allowed) ----------
__device__ float g_xT [(size_t)DM * SQ];          // x transposed   [k][m]
__device__ float g_wqT[(size_t)DM * DM];          // Wq transposed  [k][n]
__device__ float g_wkT[(size_t)DM * KN];          // Wk transposed  [k][n]
__device__ float g_qp [(size_t)2 * SQ * DM];      // Q projection K-split partials
__device__ float g_kp [(size_t)2 * SQ * KN];      // K projection K-split partials
__device__ float g_v  [(size_t)SQ * KN];
__device__ float g_qr [(size_t)NH  * SQ * HD];
__device__ float g_kr [(size_t)NKV * SQ * HD];
__device__ bf16  g_scb[(size_t)NH * SQ * SQ];     // screening scores, bf16 (128 MB)
__device__ bf16  g_x3 [(size_t)SQ * K3P];
__device__ bf16  g_wv3[(size_t)KN * K3P];
__device__ bf16  g_wo3[(size_t)DM * K3P];
__device__ bf16  g_qr1[(size_t)NH  * SQ * HD];
__device__ bf16  g_kr1[(size_t)NKV * SQ * HD];
__device__ bf16  g_at3[(size_t)SQ * K3P];

// ================= packed fp32x2 helpers (sm_100+ base ISA) =================
__device__ __forceinline__ ull pack2(float x, float y) {
    ull r;
    asm("mov.b64 %0, {%1,%2};" : "=l"(r) : "f"(x), "f"(y));
    return r;
}
__device__ __forceinline__ void unpack2(ull v, float& x, float& y) {
    asm("mov.b64 {%0,%1}, %2;" : "=f"(x), "=f"(y) : "l"(v));
}
__device__ __forceinline__ void ffma2(ull& d, ull a, ull b) {
    asm("fma.rn.f32x2 %0, %1, %2, %3;" : "=l"(d) : "l"(a), "l"(b), "l"(d));
}
__device__ __forceinline__ uint32_t smem_u32(const void* p) {
    uint32_t a;
    asm("{ .reg .u64 t; cvta.to.shared.u64 t, %1; cvt.u32.u64 %0, t; }" : "=r"(a) : "l"(p));
    return a;
}

// ================= 32x32 tiled transpose: src[R][C] -> dst[C][R] ============
__global__ void transpose_kernel(const float* __restrict__ src,
                                 float* __restrict__ dst, int R, int C)
{
    __shared__ float tile[32][33];
    int bx = blockIdx.x * 32, by = blockIdx.y * 32;
    int tx = threadIdx.x, ty = threadIdx.y;
#pragma unroll
    for (int j = 0; j < 32; j += 8)
        tile[ty + j][tx] = src[(size_t)(by + ty + j) * C + bx + tx];
    __syncthreads();
#pragma unroll
    for (int j = 0; j < 32; j += 8)
        dst[(size_t)(bx + ty + j) * R + by + tx] = tile[tx][ty + j];
}

// ============ fused Q+K fp32 projection, cp.async 3-stage, 16x8 tile ========
// grid (24, 8, 2): x<16 -> Q tile, else K tile; z = K half. Block tile 256x128.
// Inputs are k-major transposed buffers; tiles land in [kk][row] layout via
// contiguous cp.async. Per-element FMA chain ascends k exactly as rounds 9-12
// -> g_q/g_k bit-identical.
#define QK_STAGES 3
#define QK_A_BYTES 16384u           // 16 kk x 256 m x 4B
#define QK_B_BYTES 8192u            // 16 kk x 128 n x 4B
#define QK_STAGE_BYTES (QK_A_BYTES + QK_B_BYTES)   // 24576
#define QK_SMEM (QK_STAGES * 24576)                // 73728

__device__ __forceinline__ void qk_cp_tile(uint32_t smA, uint32_t smB,
                                           const float* __restrict__ At, long mcol0,
                                           const float* __restrict__ Bt, long ncol0,
                                           int k0, int ldA, int ldB, int tid) {
    // A: 16 kk-rows x 1024 bytes, 1024 transfers of 16B
#pragma unroll
    for (int it = 0; it < 4; it++) {
        int idx = tid + it * 256;          // 0..1023
        int kk  = idx >> 6;                // 0..15
        int c16 = (idx & 63) * 16;         // byte offset in row
        const void* ga = (const char*)(At + (long)(k0 + kk) * ldA + mcol0) + c16;
        asm volatile("cp.async.cg.shared.global [%0], [%1], 16;"
                     :: "r"(smA + (uint32_t)(kk * 1024 + c16)), "l"(ga));
    }
    // B: 16 kk-rows x 512 bytes, 512 transfers of 16B
#pragma unroll
    for (int it = 0; it < 2; it++) {
        int idx = tid + it * 256;          // 0..511
        int kk  = idx >> 5;                // 0..15
        int c16 = (idx & 31) * 16;
        const void* gb = (const char*)(Bt + (long)(k0 + kk) * ldB + ncol0) + c16;
        asm volatile("cp.async.cg.shared.global [%0], [%1], 16;"
                     :: "r"(smB + (uint32_t)(kk * 512 + c16)), "l"(gb));
    }
}

__global__ __launch_bounds__(256, 1) void qk_gemm()
{
    extern __shared__ char smraw[];
    uint32_t base = smem_u32(smraw);
    float* smf = (float*)smraw;

    int bx = blockIdx.x;
    bool isQ = bx < 16;
    long bcol = (long)(isQ ? bx : bx - 16) * 128;
    const float* Bt = isQ ? g_wqT : g_wkT;
    int ldB = isQ ? DM : KN;
    int N   = ldB;
    float* C = isQ ? (g_qp + (size_t)blockIdx.z * SQ * DM)
                   : (g_kp + (size_t)blockIdx.z * SQ * KN);
    long brow = (long)blockIdx.y * 256;
    int kbeg = blockIdx.z * 1024;

    int tid = threadIdx.x;
    int ty  = tid >> 4;      // 0..15 -> 16 M-rows each
    int tx  = tid & 15;      // 0..15 ->  8 N-cols each

    ull acc2[16][4];
#pragma unroll
    for (int i = 0; i < 16; i++)
#pragma unroll
        for (int j = 0; j < 4; j++) acc2[i][j] = pack2(0.f, 0.f);

    const int NC = 64;   // 1024 / 16

    // prologue: prefetch 2 chunks
#pragma unroll
    for (int s = 0; s < 2; s++) {
        uint32_t st = base + (uint32_t)s * QK_STAGE_BYTES;
        qk_cp_tile(st, st + QK_A_BYTES, g_xT, brow, Bt, bcol,
                   kbeg + s * 16, SQ, ldB, tid);
        asm volatile("cp.async.commit_group;" ::: "memory");
    }

    for (int c = 0; c < NC; c++) {
        if (c + 1 < NC) asm volatile("cp.async.wait_group 1;" ::: "memory");
        else            asm volatile("cp.async.wait_group 0;" ::: "memory");
        __syncthreads();

        if (c + 2 < NC) {
            uint32_t st = base + (uint32_t)((c + 2) % QK_STAGES) * QK_STAGE_BYTES;
            qk_cp_tile(st, st + QK_A_BYTES, g_xT, brow, Bt, bcol,
                       kbeg + (c + 2) * 16, SQ, ldB, tid);
            asm volatile("cp.async.commit_group;" ::: "memory");
        }

        const float* As = smf + ((c % QK_STAGES) * QK_STAGE_BYTES) / 4;          // [kk][256]
        const float* Bs = As + QK_A_BYTES / 4;                                   // [kk][128]

#pragma unroll
        for (int kk = 0; kk < 16; kk++) {
            const ull* bp = (const ull*)&Bs[kk * 128 + tx * 8];
            ull bb0 = bp[0], bb1 = bp[1], bb2 = bp[2], bb3 = bp[3];
            float av[16];
            *(float4*)&av[0]  = *(const float4*)&As[kk * 256 + ty * 16];
            *(float4*)&av[4]  = *(const float4*)&As[kk * 256 + ty * 16 + 4];
            *(float4*)&av[8]  = *(const float4*)&As[kk * 256 + ty * 16 + 8];
            *(float4*)&av[12] = *(const float4*)&As[kk * 256 + ty * 16 + 12];
#pragma unroll
            for (int i = 0; i < 16; i++) {
                ull a2 = pack2(av[i], av[i]);
                ffma2(acc2[i][0], a2, bb0);
                ffma2(acc2[i][1], a2, bb1);
                ffma2(acc2[i][2], a2, bb2);
                ffma2(acc2[i][3], a2, bb3);
            }
        }
        __syncthreads();
    }

#pragma unroll
    for (int i = 0; i < 16; i++) {
        long rr = brow + ty * 16 + i;
        float o[8];
#pragma unroll
        for (int j = 0; j < 4; j++) unpack2(acc2[i][j], o[2 * j], o[2 * j + 1]);
#pragma unroll
        for (int j = 0; j < 8; j++)
            C[rr * N + bcol + tx * 8 + j] = o[j];
    }
}

// ================= HMMA helpers =============================================
__device__ __forceinline__ void ldmatrix_x4(uint32_t* r, uint32_t addr) {
    asm volatile("ldmatrix.sync.aligned.m8n8.x4.shared.b16 {%0,%1,%2,%3}, [%4];"
        : "=r"(r[0]), "=r"(r[1]), "=r"(r[2]), "=r"(r[3]) : "r"(addr));
}
__device__ __forceinline__ void mma16816(float* c, const uint32_t* a, const uint32_t* b) {
    asm volatile(
        "mma.sync.aligned.m16n8k16.row.col.f32.bf16.bf16.f32 "
        "{%0,%1,%2,%3}, {%4,%5,%6,%7}, {%8,%9}, {%0,%1,%2,%3};"
        : "+f"(c[0]), "+f"(c[1]), "+f"(c[2]), "+f"(c[3])
        : "r"(a[0]), "r"(a[1]), "r"(a[2]), "r"(a[3]), "r"(b[0]), "r"(b[1]));
}
__device__ __forceinline__ uint32_t sw128(uint32_t bo) { return bo ^ ((bo >> 3) & 0x70); }

// ============ bf16 GEMM-NT with cp.async 3-stage pipeline (HMMA) ============
#define STAGES 3
#define STAGE_BYTES 32768u
#define GEMM3_SMEM (STAGES * 32768 + 256)

__device__ __forceinline__ void cp_tile(uint32_t smA, uint32_t smB,
                                        const bf16* __restrict__ A, long rowA,
                                        const bf16* __restrict__ B, long rowB,
                                        int k0, int ld, int tid) {
#pragma unroll
    for (int it = 0; it < 4; it++) {
        int idx = tid + it * 256;
        int rr  = idx >> 3;
        int c16 = (idx & 7) * 16;
        uint32_t sw = sw128((uint32_t)(rr * 128 + c16));
        const void* ga = (const char*)(A + (rowA + rr) * (long)ld + k0) + c16;
        const void* gb = (const char*)(B + (rowB + rr) * (long)ld + k0) + c16;
        asm volatile("cp.async.cg.shared.global [%0], [%1], 16;" :: "r"(smA + sw), "l"(ga));
        asm volatile("cp.async.cg.shared.global [%0], [%1], 16;" :: "r"(smB + sw), "l"(gb));
    }
}

// shared mainloop; BFOUT=0 -> fp32 C, BFOUT=1 -> bf16 C
template <int BFOUT>
__device__ __forceinline__ void gemm3_body(
    const bf16* __restrict__ Az, const bf16* __restrict__ Bz,
    float* Cz, bf16* Czb, int N, int K, float alpha)
{
    extern __shared__ char smraw[];
    uint32_t raw  = smem_u32(smraw);
    uint32_t base = (raw + 127u) & ~127u;

    long brow = (long)blockIdx.y * 128;
    long bcol = (long)blockIdx.x * 128;
    int tid  = threadIdx.x;
    int lane = tid & 31;
    int wid  = tid >> 5;
    int wm   = wid & 3;
    int wn   = wid >> 2;

    float acc[2][8][4];
#pragma unroll
    for (int i = 0; i < 2; i++)
#pragma unroll
        for (int j = 0; j < 8; j++)
#pragma unroll
            for (int q = 0; q < 4; q++) acc[i][j][q] = 0.f;

    int NC = K / 64;
    {
        int npre = NC < 2 ? NC : 2;
        for (int s = 0; s < npre; s++) {
            uint32_t st = base + (uint32_t)s * STAGE_BYTES;
            cp_tile(st, st + 16384u, Az, brow, Bz, bcol, s * 64, K, tid);
            asm volatile("cp.async.commit_group;" ::: "memory");
        }
    }

    int aRow = wm * 32 + (lane & 15);
    int aCol = (lane >> 4) * 16;
    int bRow = wn * 64 + ((lane >> 4) << 3) + (lane & 7);
    int bCol = ((lane >> 3) & 1) * 16;

    for (int c = 0; c < NC; c++) {
        if (c + 1 < NC) asm volatile("cp.async.wait_group 1;" ::: "memory");
        else            asm volatile("cp.async.wait_group 0;" ::: "memory");
        __syncthreads();

        if (c + 2 < NC) {
            uint32_t st = base + (uint32_t)((c + 2) % STAGES) * STAGE_BYTES;
            cp_tile(st, st + 16384u, Az, brow, Bz, bcol, (c + 2) * 64, K, tid);
            asm volatile("cp.async.commit_group;" ::: "memory");
        }

        uint32_t smA = base + (uint32_t)(c % STAGES) * STAGE_BYTES;
        uint32_t smB = smA + 16384u;

#pragma unroll
        for (int ks = 0; ks < 4; ks++) {
            uint32_t a[2][4];
#pragma unroll
            for (int mt = 0; mt < 2; mt++) {
                uint32_t bo = (uint32_t)((aRow + mt * 16) * 128 + aCol + ks * 32);
                ldmatrix_x4(a[mt], smA + sw128(bo));
            }
            uint32_t bb[4][4];
#pragma unroll
            for (int p = 0; p < 4; p++) {
                uint32_t bo = (uint32_t)((bRow + p * 16) * 128 + bCol + ks * 32);
                ldmatrix_x4(bb[p], smB + sw128(bo));
            }
#pragma unroll
            for (int mt = 0; mt < 2; mt++)
#pragma unroll
                for (int nt = 0; nt < 8; nt++)
                    mma16816(acc[mt][nt], a[mt], &bb[nt >> 1][(nt & 1) * 2]);
        }
        __syncthreads();
    }

    long r0 = brow + wm * 32 + (lane >> 2);
    long c0 = bcol + wn * 64 + (lane & 3) * 2;
#pragma unroll
    for (int mt = 0; mt < 2; mt++) {
#pragma unroll
        for (int nt = 0; nt < 8; nt++) {
            long rr = r0 + mt * 16;
            long cc = c0 + nt * 8;
            if (BFOUT) {
                __nv_bfloat162 v0 = __floats2bfloat162_rn(alpha * acc[mt][nt][0], alpha * acc[mt][nt][1]);
                __nv_bfloat162 v1 = __floats2bfloat162_rn(alpha * acc[mt][nt][2], alpha * acc[mt][nt][3]);
                *(__nv_bfloat162*)(Czb + rr * N + cc)       = v0;
                *(__nv_bfloat162*)(Czb + (rr + 8) * N + cc) = v1;
            } else {
                float2 v0 = make_float2(alpha * acc[mt][nt][0], alpha * acc[mt][nt][1]);
                float2 v1 = make_float2(alpha * acc[mt][nt][2], alpha * acc[mt][nt][3]);
                *(float2*)(Cz + rr * N + cc)       = v0;
                *(float2*)(Cz + (rr + 8) * N + cc) = v1;
            }
        }
    }
}

__global__ __launch_bounds__(256, 1) void gemm3_cp(
    const bf16* __restrict__ A, const bf16* __restrict__ B, float* __restrict__ C,
    int N, int K, long sA, long sB, long sC, float alpha, int bDiv)
{
    const bf16* Az = A + (long)blockIdx.z * sA;
    const bf16* Bz = B + (long)(blockIdx.z / bDiv) * sB;
    float*      Cz = C + (long)blockIdx.z * sC;
    gemm3_body<0>(Az, Bz, Cz, nullptr, N, K, alpha);
}

__global__ __launch_bounds__(256, 1) void gemm3_cp_bf(
    const bf16* __restrict__ A, const bf16* __restrict__ B, bf16* __restrict__ C,
    int N, int K, long sA, long sB, long sC, float alpha, int bDiv)
{
    const bf16* Az = A + (long)blockIdx.z * sA;
    const bf16* Bz = B + (long)(blockIdx.z / bDiv) * sB;
    bf16*       Cz = C + (long)blockIdx.z * sC;
    gemm3_body<1>(Az, Bz, nullptr, Cz, N, K, alpha);
}

// ================= fp32 -> bf16x3 limb conversion ===========================
// A-type row: [h1 | h1 | h2]    B-type row: [h1 | h2 | h1]
__global__ void conv3_kernel(const float4* __restrict__ src, bf16* __restrict__ dst,
                             long n4, int Kq, int isA)
{
    long i = (long)blockIdx.x * blockDim.x + threadIdx.x;
    if (i >= n4) return;
    long r  = i / Kq;
    int  c4 = (int)(i - r * Kq) * 4;
    int  K  = Kq * 4;
    float4 f = src[i];
    union { bf16 h[4]; uint2 u; } H1, H2;
    float fa[4] = {f.x, f.y, f.z, f.w};
#pragma unroll
    for (int j = 0; j < 4; j++) {
        H1.h[j] = __float2bfloat16(fa[j]);
        H2.h[j] = __float2bfloat16(fa[j] - __bfloat162float(H1.h[j]));
    }
    bf16* d = dst + r * (long)(3 * K) + c4;
    *(uint2*)(d)         = H1.u;
    *(uint2*)(d + K)     = isA ? H1.u : H2.u;
    *(uint2*)(d + 2 * K) = isA ? H2.u : H1.u;
}

// ================= rms-norm + rope (fused partial-halves add) ===============
__device__ __forceinline__ float blockSum128(float v, float* red) {
#pragma unroll
    for (int o = 16; o > 0; o >>= 1) v += __shfl_down_sync(0xffffffffu, v, o);
    if ((threadIdx.x & 31) == 0) red[threadIdx.x >> 5] = v;
    __syncthreads();
    return red[0] + red[1] + red[2] + red[3];
}

__global__ void rope_q_kernel(const float* __restrict__ cosb,
                              const float* __restrict__ sinb,
                              const float* __restrict__ w)
{
    int s = blockIdx.x, h = blockIdx.y, d = threadIdx.x;
    __shared__ float red[4];
    __shared__ float sh[HD];
    size_t off = (size_t)s * DM + h * HD + d;
    float v = g_qp[off] + g_qp[(size_t)SQ * DM + off];   // half0 + half1
    float ss = blockSum128(v * v, red);
    float inv = rsqrtf(ss * (1.0f / HD) + 1e-6f);
    float qn = v * inv * w[d];
    sh[d] = qn;
    __syncthreads();
    float rot = (d < 64) ? -sh[d + 64] : sh[d - 64];
    float f = qn * cosb[s * HD + d] + rot * sinb[s * HD + d];
    g_qr [((size_t)h * SQ + s) * HD + d] = f;
    g_qr1[((size_t)h * SQ + s) * HD + d] = __float2bfloat16(f);
}

__global__ void rope_k_kernel(const float* __restrict__ cosb,
                              const float* __restrict__ sinb,
                              const float* __restrict__ w)
{
    int s = blockIdx.x, h = blockIdx.y, d = threadIdx.x;
    __shared__ float red[4];
    __shared__ float sh[HD];
    size_t off = (size_t)s * KN + h * HD + d;
    float v = g_kp[off] + g_kp[(size_t)SQ * KN + off];   // half0 + half1
    float ss = blockSum128(v * v, red);
    float inv = rsqrtf(ss * (1.0f / HD) + 1e-6f);
    float kn = v * inv * w[d];
    sh[d] = kn;
    __syncthreads();
    float rot = (d < 64) ? -sh[d + 64] : sh[d - 64];
    float f = kn * cosb[s * HD + d] + rot * sinb[s * HD + d];
    g_kr [((size_t)h * SQ + s) * HD + d] = f;
    g_kr1[((size_t)h * SQ + s) * HD + d] = __float2bfloat16(f);
}

// ================= screening + exact rescore + softmax + sparse PV ==========
__device__ __forceinline__ unsigned fkey(float f) {
    unsigned u = __float_as_uint(f);
    return (u & 0x80000000u) ? ~u : (u | 0x80000000u);
}
__device__ __forceinline__ float unfkey(unsigned u) {
    unsigned v = (u & 0x80000000u) ? (u & 0x7FFFFFFFu) : ~u;
    return __uint_as_float(v);
}

#define CAP 320

__global__ void attn_select_kernel()
{
    int row = blockIdx.x, h = blockIdx.y;
    int kvh = h >> 1;
    int t = threadIdx.x;
    int lane = t & 31;
    int wid  = t >> 5;
    const uint4* srow = (const uint4*)(g_scb + ((size_t)h * SQ + row) * SQ);

    // 16 bf16 scores per thread via 2 x uint4 (8 bf16 each)
    float    val[16];
    unsigned key[16];
#pragma unroll
    for (int i = 0; i < 2; i++) {
        uint4 u = srow[t + i * 128];
        unsigned ws[4] = {u.x, u.y, u.z, u.w};
#pragma unroll
        for (int wq = 0; wq < 4; wq++) {
            float lo = __bfloat162float(__ushort_as_bfloat16((unsigned short)(ws[wq] & 0xFFFFu)));
            float hi = __bfloat162float(__ushort_as_bfloat16((unsigned short)(ws[wq] >> 16)));
            int j = i * 8 + wq * 2;
            val[j] = lo;     key[j]     = fkey(lo);
            val[j + 1] = hi; key[j + 1] = fkey(hi);
        }
    }

    __shared__ float redf[4];
    __shared__ int   redc[2][4];

    // approx threshold key: prefix binary search over top 16 bits only.
    unsigned thrKey = 0u;
#pragma unroll
    for (int b = 31; b >= 16; b--) {
        unsigned cand = thrKey | (1u << b);
        int c = 0;
#pragma unroll
        for (int i = 0; i < 16; i++) c += (key[i] >= cand);
        c = __reduce_add_sync(0xffffffffu, c);
        int buf = b & 1;
        if (lane == 0) redc[buf][wid] = c;
        __syncthreads();
        int cnt = redc[buf][0] + redc[buf][1] + redc[buf][2] + redc[buf][3];
        if (cnt >= TOPK) thrKey = cand;
    }
    // adaptive band: covers bf16 score-storage + screening GEMM error
    float thr  = unfkey(thrKey);
    float band = thr - (0.06f + 0.01f * fabsf(thr));

    // band mask + deterministic compaction; col of val[j] = 8*(t + (j>>3)*128) + (j&7)
    unsigned mask = 0;
#pragma unroll
    for (int i = 0; i < 16; i++) {
        int col = 8 * (t + (i >> 3) * 128) + (i & 7);
        if (val[i] >= band || col == row) mask |= (1u << i);
    }
    int mc = __popc(mask);

    __shared__ int cnts[129];
    cnts[t] = mc;
    __syncthreads();
    if (t == 0) {
        int a = 0;
        for (int x = 0; x < 128; x++) { int c = cnts[x]; cnts[x] = a; a += c; }
        cnts[128] = a;
    }
    __syncthreads();
    int total = cnts[128];
    if (total > CAP) total = CAP;

    __shared__ int    sIdx[CAP];
    __shared__ float  sEx[CAP];
    __shared__ float  sP[CAP];
    __shared__ float4 sQ4[32];
    {
        int p = cnts[t];
#pragma unroll
        for (int i = 0; i < 16; i++) {
            if (mask & (1u << i)) {
                if (p < CAP) sIdx[p] = 8 * (t + (i >> 3) * 128) + (i & 7);
                p++;
            }
        }
    }
    if (t < 32) sQ4[t] = ((const float4*)(g_qr + ((size_t)h * SQ + row) * HD))[t];
    __syncthreads();

    // exact fp32 rescore: one warp per candidate, float4 coalesced loads
    for (int c = wid; c < total; c += 4) {
        const float4* kp = (const float4*)(g_kr + ((size_t)kvh * SQ + sIdx[c]) * HD);
        float4 k4 = kp[lane];
        float4 q4 = sQ4[lane];
        float part = q4.x * k4.x;
        part = fmaf(q4.y, k4.y, part);
        part = fmaf(q4.z, k4.z, part);
        part = fmaf(q4.w, k4.w, part);
#pragma unroll
        for (int o = 16; o > 0; o >>= 1) part += __shfl_down_sync(0xffffffffu, part, o);
        if (lane == 0) sEx[c] = SCALE * part;
    }
    __syncthreads();

    // exact row max over candidates
    float m = -3.4e38f;
    for (int c = t; c < total; c += 128) m = fmaxf(m, sEx[c]);
#pragma unroll
    for (int o = 16; o > 0; o >>= 1) m = fmaxf(m, __shfl_down_sync(0xffffffffu, m, o));
    if (lane == 0) redf[wid] = m;
    __syncthreads();
    float rowmax = fmaxf(fmaxf(redf[0], redf[1]), fmaxf(redf[2], redf[3]));

    // exact top-40 membership among candidates
    for (int c = t; c < total; c += 128) {
        float v = sEx[c];
        int cnt = 0;
        for (int c2 = 0; c2 < total; c2++) cnt += (sEx[c2] > v);
        bool kept = (cnt < TOPK) || (sIdx[c] == row);
        sP[c] = kept ? __expf(v - rowmax) : 0.f;
    }
    __syncthreads();

    // denominator
    float ps = 0.f;
    for (int c = t; c < total; c += 128) ps += sP[c];
#pragma unroll
    for (int o = 16; o > 0; o >>= 1) ps += __shfl_down_sync(0xffffffffu, ps, o);
    if (lane == 0) redf[wid] = ps;
    __syncthreads();
    float denom = redf[0] + redf[1] + redf[2] + redf[3];

    // sparse PV (coalesced v rows)
    float acc = 0.f;
    for (int c = 0; c < total; c++)
        acc += sP[c] * g_v[(size_t)sIdx[c] * KN + kvh * HD + t];

    float o = acc / denom;
    bf16 h1 = __float2bfloat16(o);
    bf16 h2 = __float2bfloat16(o - __bfloat162float(h1));
    bf16* dst = g_at3 + (size_t)row * K3P;
    int col = h * HD + t;
    dst[col] = h1; dst[DM + col] = h1; dst[2 * DM + col] = h2;   // A-type
}

// ================= launch (single stream — linear graph) =====================
extern "C" void kernel_launch(void* const* d_in, const int* in_sizes, int n_in,
                              void* d_out, int out_size)
{
    const float* x    = (const float*)d_in[0];
    const float* cosb = (const float*)d_in[1];
    const float* sinb = (const float*)d_in[2];
    const float* Wq   = (const float*)d_in[3];
    const float* Wk   = (const float*)d_in[4];
    const float* Wv   = (const float*)d_in[5];
    const float* Wo   = (const float*)d_in[6];
    const float* qw   = (const float*)d_in[7];
    const float* kw   = (const float*)d_in[8];
    float* out = (float*)d_out;

    float *pv, *pxT, *pwqT, *pwkT;
    bf16  *pscb, *px3, *pwv3, *pwo3, *pqr1, *pkr1, *pat3;
    cudaGetSymbolAddress((void**)&pv,   g_v);
    cudaGetSymbolAddress((void**)&pxT,  g_xT);
    cudaGetSymbolAddress((void**)&pwqT, g_wqT);
    cudaGetSymbolAddress((void**)&pwkT, g_wkT);
    cudaGetSymbolAddress((void**)&pscb, g_scb);
    cudaGetSymbolAddress((void**)&px3,  g_x3);
    cudaGetSymbolAddress((void**)&pwv3, g_wv3);
    cudaGetSymbolAddress((void**)&pwo3, g_wo3);
    cudaGetSymbolAddress((void**)&pqr1, g_qr1);
    cudaGetSymbolAddress((void**)&pkr1, g_kr1);
    cudaGetSymbolAddress((void**)&pat3, g_at3);

    static bool attr_done = false;
    if (!attr_done) {
        cudaFuncSetAttribute(gemm3_cp,    cudaFuncAttributeMaxDynamicSharedMemorySize, GEMM3_SMEM);
        cudaFuncSetAttribute(gemm3_cp_bf, cudaFuncAttributeMaxDynamicSharedMemorySize, GEMM3_SMEM);
        cudaFuncSetAttribute(qk_gemm,     cudaFuncAttributeMaxDynamicSharedMemorySize, QK_SMEM);
        attr_done = true;
    }

    // transposes for cp.async k-major tiles (x, Wq, Wk)
    transpose_kernel<<<dim3(DM / 32, SQ / 32), dim3(32, 8)>>>(x,  pxT,  SQ, DM);
    transpose_kernel<<<dim3(DM / 32, DM / 32), dim3(32, 8)>>>(Wq, pwqT, DM, DM);
    transpose_kernel<<<dim3(DM / 32, KN / 32), dim3(32, 8)>>>(Wk, pwkT, KN, DM);

    // limb conversions (x, Wv, Wo)
    {
        long n4;
        n4 = (long)SQ * DM / 4;
        conv3_kernel<<<(unsigned)((n4 + 255) / 256), 256>>>((const float4*)x,  px3,  n4, DM / 4, 1);
        n4 = (long)KN * DM / 4;
        conv3_kernel<<<(unsigned)((n4 + 255) / 256), 256>>>((const float4*)Wv, pwv3, n4, DM / 4, 0);
        n4 = (long)DM * DM / 4;
        conv3_kernel<<<(unsigned)((n4 + 255) / 256), 256>>>((const float4*)Wo, pwo3, n4, DM / 4, 0);
    }

    // fused Q+K fp32 projection (cp.async 3-stage, 16x8 tile, K-split x2)
    qk_gemm<<<dim3(24, 8, 2), 256, QK_SMEM>>>();

    // V projection: bf16x3 HMMA
    gemm3_cp<<<dim3(KN / 128, SQ / 128, 1), 256, GEMM3_SMEM>>>(px3, pwv3, pv, KN, K3P, 0, 0, 0, 1.f, 1);

    // rms-norm + rope (fp32 + plain-bf16 screening copies; adds K-split halves)
    rope_q_kernel<<<dim3(SQ, NH),  128>>>(cosb, sinb, qw);
    rope_k_kernel<<<dim3(SQ, NKV), 128>>>(cosb, sinb, kw);

    // screening scores: plain bf16 inputs AND bf16 output buffer
    gemm3_cp_bf<<<dim3(SQ / 128, SQ / 128, NH), 256, GEMM3_SMEM>>>(
        pqr1, pkr1, pscb, SQ, HD,
        (long)SQ * HD, (long)SQ * HD, (long)SQ * SQ, SCALE, 2);

    // screening + exact fp32 rescore + softmax + sparse PV
    attn_select_kernel<<<dim3(SQ, NH), 128>>>();

    // O projection: bf16x3 HMMA
    gemm3_cp<<<dim3(DM / 128, SQ / 128, 1), 256, GEMM3_SMEM>>>(pat3, pwo3, out, DM, K3P, 0, 0, 0, 1.f, 1);
}

// round 16
// speedup vs baseline: 1.0319x; 1.0317x over previous
#include <cuda_runtime.h>
#include <cuda_bf16.h>
#include <math.h>
#include <stdint.h>

typedef __nv_bfloat16 bf16;
typedef unsigned long long ull;

#define SQ 2048
#define DM 2048
#define NH 16
#define NKV 8
#define HD 128
#define KN (NKV*HD)          // 1024
#define TOPK 40
#define SCALE 0.08838834764831845f  // 128^-0.5

// ---------------- scratch (device globals; no allocations allowed) ----------
__device__ float g_xT [(size_t)DM * SQ];          // x transposed   [k][m]
__device__ float g_wqT[(size_t)DM * DM];          // Wq transposed  [k][n]
__device__ float g_wkT[(size_t)DM * KN];          // Wk transposed  [k][n]
__device__ float g_qp [(size_t)2 * SQ * DM];      // Q projection K-split partials
__device__ float g_kp [(size_t)2 * SQ * KN];      // K projection K-split partials
__device__ float g_v  [(size_t)SQ * KN];
__device__ float g_qr [(size_t)NH  * SQ * HD];
__device__ float g_kr [(size_t)NKV * SQ * HD];
__device__ bf16  g_scb[(size_t)NH * SQ * SQ];     // screening scores, bf16 (128 MB)
__device__ bf16  g_xh1[(size_t)SQ * DM];          // x limbs
__device__ bf16  g_xh2[(size_t)SQ * DM];
__device__ bf16  g_wvh1[(size_t)KN * DM];         // Wv limbs
__device__ bf16  g_wvh2[(size_t)KN * DM];
__device__ bf16  g_woh1[(size_t)DM * DM];         // Wo limbs
__device__ bf16  g_woh2[(size_t)DM * DM];
__device__ bf16  g_ath1[(size_t)SQ * DM];         // attention out limbs
__device__ bf16  g_ath2[(size_t)SQ * DM];
__device__ bf16  g_qr1[(size_t)NH  * SQ * HD];
__device__ bf16  g_kr1[(size_t)NKV * SQ * HD];

// ================= packed fp32x2 helpers (sm_100+ base ISA) =================
__device__ __forceinline__ ull pack2(float x, float y) {
    ull r;
    asm("mov.b64 %0, {%1,%2};" : "=l"(r) : "f"(x), "f"(y));
    return r;
}
__device__ __forceinline__ void unpack2(ull v, float& x, float& y) {
    asm("mov.b64 {%0,%1}, %2;" : "=f"(x), "=f"(y) : "l"(v));
}
__device__ __forceinline__ void ffma2(ull& d, ull a, ull b) {
    asm("fma.rn.f32x2 %0, %1, %2, %3;" : "=l"(d) : "l"(a), "l"(b), "l"(d));
}
__device__ __forceinline__ uint32_t smem_u32(const void* p) {
    uint32_t a;
    asm("{ .reg .u64 t; cvta.to.shared.u64 t, %1; cvt.u32.u64 %0, t; }" : "=r"(a) : "l"(p));
    return a;
}

// ================= 32x32 tiled transpose: src[R][C] -> dst[C][R] ============
__global__ void transpose_kernel(const float* __restrict__ src,
                                 float* __restrict__ dst, int R, int C)
{
    __shared__ float tile[32][33];
    int bx = blockIdx.x * 32, by = blockIdx.y * 32;
    int tx = threadIdx.x, ty = threadIdx.y;
#pragma unroll
    for (int j = 0; j < 32; j += 8)
        tile[ty + j][tx] = src[(size_t)(by + ty + j) * C + bx + tx];
    __syncthreads();
#pragma unroll
    for (int j = 0; j < 32; j += 8)
        dst[(size_t)(bx + ty + j) * R + by + tx] = tile[tx][ty + j];
}

// ============ fused Q+K fp32 projection, cp.async 3-stage, 16x8 tile ========
#define QK_STAGES 3
#define QK_A_BYTES 16384u
#define QK_B_BYTES 8192u
#define QK_STAGE_BYTES (QK_A_BYTES + QK_B_BYTES)
#define QK_SMEM (QK_STAGES * 24576)

__device__ __forceinline__ void qk_cp_tile(uint32_t smA, uint32_t smB,
                                           const float* __restrict__ At, long mcol0,
                                           const float* __restrict__ Bt, long ncol0,
                                           int k0, int ldA, int ldB, int tid) {
#pragma unroll
    for (int it = 0; it < 4; it++) {
        int idx = tid + it * 256;
        int kk  = idx >> 6;
        int c16 = (idx & 63) * 16;
        const void* ga = (const char*)(At + (long)(k0 + kk) * ldA + mcol0) + c16;
        asm volatile("cp.async.cg.shared.global [%0], [%1], 16;"
                     :: "r"(smA + (uint32_t)(kk * 1024 + c16)), "l"(ga));
    }
#pragma unroll
    for (int it = 0; it < 2; it++) {
        int idx = tid + it * 256;
        int kk  = idx >> 5;
        int c16 = (idx & 31) * 16;
        const void* gb = (const char*)(Bt + (long)(k0 + kk) * ldB + ncol0) + c16;
        asm volatile("cp.async.cg.shared.global [%0], [%1], 16;"
                     :: "r"(smB + (uint32_t)(kk * 512 + c16)), "l"(gb));
    }
}

__global__ __launch_bounds__(256, 1) void qk_gemm()
{
    extern __shared__ char smraw[];
    uint32_t base = smem_u32(smraw);
    float* smf = (float*)smraw;

    int bx = blockIdx.x;
    bool isQ = bx < 16;
    long bcol = (long)(isQ ? bx : bx - 16) * 128;
    const float* Bt = isQ ? g_wqT : g_wkT;
    int ldB = isQ ? DM : KN;
    int N   = ldB;
    float* C = isQ ? (g_qp + (size_t)blockIdx.z * SQ * DM)
                   : (g_kp + (size_t)blockIdx.z * SQ * KN);
    long brow = (long)blockIdx.y * 256;
    int kbeg = blockIdx.z * 1024;

    int tid = threadIdx.x;
    int ty  = tid >> 4;
    int tx  = tid & 15;

    ull acc2[16][4];
#pragma unroll
    for (int i = 0; i < 16; i++)
#pragma unroll
        for (int j = 0; j < 4; j++) acc2[i][j] = pack2(0.f, 0.f);

    const int NC = 64;
#pragma unroll
    for (int s = 0; s < 2; s++) {
        uint32_t st = base + (uint32_t)s * QK_STAGE_BYTES;
        qk_cp_tile(st, st + QK_A_BYTES, g_xT, brow, Bt, bcol,
                   kbeg + s * 16, SQ, ldB, tid);
        asm volatile("cp.async.commit_group;" ::: "memory");
    }

    for (int c = 0; c < NC; c++) {
        if (c + 1 < NC) asm volatile("cp.async.wait_group 1;" ::: "memory");
        else            asm volatile("cp.async.wait_group 0;" ::: "memory");
        __syncthreads();

        if (c + 2 < NC) {
            uint32_t st = base + (uint32_t)((c + 2) % QK_STAGES) * QK_STAGE_BYTES;
            qk_cp_tile(st, st + QK_A_BYTES, g_xT, brow, Bt, bcol,
                       kbeg + (c + 2) * 16, SQ, ldB, tid);
            asm volatile("cp.async.commit_group;" ::: "memory");
        }

        const float* As = smf + ((c % QK_STAGES) * QK_STAGE_BYTES) / 4;
        const float* Bs = As + QK_A_BYTES / 4;

#pragma unroll
        for (int kk = 0; kk < 16; kk++) {
            const ull* bp = (const ull*)&Bs[kk * 128 + tx * 8];
            ull bb0 = bp[0], bb1 = bp[1], bb2 = bp[2], bb3 = bp[3];
            float av[16];
            *(float4*)&av[0]  = *(const float4*)&As[kk * 256 + ty * 16];
            *(float4*)&av[4]  = *(const float4*)&As[kk * 256 + ty * 16 + 4];
            *(float4*)&av[8]  = *(const float4*)&As[kk * 256 + ty * 16 + 8];
            *(float4*)&av[12] = *(const float4*)&As[kk * 256 + ty * 16 + 12];
#pragma unroll
            for (int i = 0; i < 16; i++) {
                ull a2 = pack2(av[i], av[i]);
                ffma2(acc2[i][0], a2, bb0);
                ffma2(acc2[i][1], a2, bb1);
                ffma2(acc2[i][2], a2, bb2);
                ffma2(acc2[i][3], a2, bb3);
            }
        }
        __syncthreads();
    }

#pragma unroll
    for (int i = 0; i < 16; i++) {
        long rr = brow + ty * 16 + i;
        float o[8];
#pragma unroll
        for (int j = 0; j < 4; j++) unpack2(acc2[i][j], o[2 * j], o[2 * j + 1]);
#pragma unroll
        for (int j = 0; j < 8; j++)
            C[rr * N + bcol + tx * 8 + j] = o[j];
    }
}

// ================= HMMA helpers =============================================
__device__ __forceinline__ void ldmatrix_x4(uint32_t* r, uint32_t addr) {
    asm volatile("ldmatrix.sync.aligned.m8n8.x4.shared.b16 {%0,%1,%2,%3}, [%4];"
        : "=r"(r[0]), "=r"(r[1]), "=r"(r[2]), "=r"(r[3]) : "r"(addr));
}
__device__ __forceinline__ void mma16816(float* c, const uint32_t* a, const uint32_t* b) {
    asm volatile(
        "mma.sync.aligned.m16n8k16.row.col.f32.bf16.bf16.f32 "
        "{%0,%1,%2,%3}, {%4,%5,%6,%7}, {%8,%9}, {%0,%1,%2,%3};"
        : "+f"(c[0]), "+f"(c[1]), "+f"(c[2]), "+f"(c[3])
        : "r"(a[0]), "r"(a[1]), "r"(a[2]), "r"(a[3]), "r"(b[0]), "r"(b[1]));
}
__device__ __forceinline__ uint32_t sw128(uint32_t bo) { return bo ^ ((bo >> 3) & 0x70); }

// ============ 2-limb bf16 GEMM-NT, 3 passes/chunk, cp.async 2-stage =========
// C[M,N] = (Ah1+Ah2)[M,K] @ (Bh1+Bh2)[N,K]^T  (dropping h2*h2 term)
#define L_TILE 16384u
#define L_STAGE_BYTES (4u * L_TILE)   // Ah1,Ah2,Bh1,Bh2
#define GEMM2L_SMEM (2 * 4 * 16384)   // 128 KB

__device__ __forceinline__ void cp_one(uint32_t sm, const bf16* __restrict__ src,
                                       long row0, int k0, int ld, int tid) {
#pragma unroll
    for (int it = 0; it < 4; it++) {
        int idx = tid + it * 256;
        int rr  = idx >> 3;
        int c16 = (idx & 7) * 16;
        uint32_t sw = sw128((uint32_t)(rr * 128 + c16));
        const void* g = (const char*)(src + (row0 + rr) * (long)ld + k0) + c16;
        asm volatile("cp.async.cg.shared.global [%0], [%1], 16;" :: "r"(sm + sw), "l"(g));
    }
}

__global__ __launch_bounds__(256, 1) void gemm2l(
    const bf16* __restrict__ Ah1, const bf16* __restrict__ Ah2,
    const bf16* __restrict__ Bh1, const bf16* __restrict__ Bh2,
    float* __restrict__ C, int N, int K)
{
    extern __shared__ char smraw[];
    uint32_t base = smem_u32(smraw);

    long brow = (long)blockIdx.y * 128;
    long bcol = (long)blockIdx.x * 128;
    int tid  = threadIdx.x;
    int lane = tid & 31;
    int wid  = tid >> 5;
    int wm   = wid & 3;
    int wn   = wid >> 2;

    float acc[2][8][4];
#pragma unroll
    for (int i = 0; i < 2; i++)
#pragma unroll
        for (int j = 0; j < 8; j++)
#pragma unroll
            for (int q = 0; q < 4; q++) acc[i][j][q] = 0.f;

    int NC = K / 64;

    // prologue: chunk 0 into stage 0
    {
        uint32_t st = base;
        cp_one(st,               Ah1, brow, 0, K, tid);
        cp_one(st + L_TILE,      Ah2, brow, 0, K, tid);
        cp_one(st + 2 * L_TILE,  Bh1, bcol, 0, K, tid);
        cp_one(st + 3 * L_TILE,  Bh2, bcol, 0, K, tid);
        asm volatile("cp.async.commit_group;" ::: "memory");
    }

    int aRow = wm * 32 + (lane & 15);
    int aCol = (lane >> 4) * 16;
    int bRow = wn * 64 + ((lane >> 4) << 3) + (lane & 7);
    int bCol = ((lane >> 3) & 1) * 16;

    for (int c = 0; c < NC; c++) {
        if (c + 1 < NC) {
            uint32_t st = base + (uint32_t)((c + 1) & 1) * L_STAGE_BYTES;
            int k0 = (c + 1) * 64;
            cp_one(st,               Ah1, brow, k0, K, tid);
            cp_one(st + L_TILE,      Ah2, brow, k0, K, tid);
            cp_one(st + 2 * L_TILE,  Bh1, bcol, k0, K, tid);
            cp_one(st + 3 * L_TILE,  Bh2, bcol, k0, K, tid);
            asm volatile("cp.async.commit_group;" ::: "memory");
            asm volatile("cp.async.wait_group 1;" ::: "memory");
        } else {
            asm volatile("cp.async.wait_group 0;" ::: "memory");
        }
        __syncthreads();

        uint32_t st = base + (uint32_t)(c & 1) * L_STAGE_BYTES;
        // passes: (Ah1,Bh1), (Ah1,Bh2), (Ah2,Bh1)
#pragma unroll
        for (int pass = 0; pass < 3; pass++) {
            uint32_t smA = st + ((pass == 2) ? L_TILE : 0u);
            uint32_t smB = st + 2 * L_TILE + ((pass == 1) ? L_TILE : 0u);
#pragma unroll
            for (int ks = 0; ks < 4; ks++) {
                uint32_t a[2][4];
#pragma unroll
                for (int mt = 0; mt < 2; mt++) {
                    uint32_t bo = (uint32_t)((aRow + mt * 16) * 128 + aCol + ks * 32);
                    ldmatrix_x4(a[mt], smA + sw128(bo));
                }
                uint32_t bb[4][4];
#pragma unroll
                for (int p = 0; p < 4; p++) {
                    uint32_t bo = (uint32_t)((bRow + p * 16) * 128 + bCol + ks * 32);
                    ldmatrix_x4(bb[p], smB + sw128(bo));
                }
#pragma unroll
                for (int mt = 0; mt < 2; mt++)
#pragma unroll
                    for (int nt = 0; nt < 8; nt++)
                        mma16816(acc[mt][nt], a[mt], &bb[nt >> 1][(nt & 1) * 2]);
            }
        }
        __syncthreads();
    }

    long r0 = brow + wm * 32 + (lane >> 2);
    long c0 = bcol + wn * 64 + (lane & 3) * 2;
#pragma unroll
    for (int mt = 0; mt < 2; mt++) {
#pragma unroll
        for (int nt = 0; nt < 8; nt++) {
            long rr = r0 + mt * 16;
            long cc = c0 + nt * 8;
            *(float2*)(C + rr * N + cc)       = make_float2(acc[mt][nt][0], acc[mt][nt][1]);
            *(float2*)(C + (rr + 8) * N + cc) = make_float2(acc[mt][nt][2], acc[mt][nt][3]);
        }
    }
}

// ============ plain bf16 GEMM-NT (screening), cp.async 3-stage, bf16 out ====
#define STAGES 3
#define STAGE_BYTES 32768u
#define GEMM3_SMEM (STAGES * 32768 + 256)

__device__ __forceinline__ void cp_tile(uint32_t smA, uint32_t smB,
                                        const bf16* __restrict__ A, long rowA,
                                        const bf16* __restrict__ B, long rowB,
                                        int k0, int ld, int tid) {
#pragma unroll
    for (int it = 0; it < 4; it++) {
        int idx = tid + it * 256;
        int rr  = idx >> 3;
        int c16 = (idx & 7) * 16;
        uint32_t sw = sw128((uint32_t)(rr * 128 + c16));
        const void* ga = (const char*)(A + (rowA + rr) * (long)ld + k0) + c16;
        const void* gb = (const char*)(B + (rowB + rr) * (long)ld + k0) + c16;
        asm volatile("cp.async.cg.shared.global [%0], [%1], 16;" :: "r"(smA + sw), "l"(ga));
        asm volatile("cp.async.cg.shared.global [%0], [%1], 16;" :: "r"(smB + sw), "l"(gb));
    }
}

__global__ __launch_bounds__(256, 1) void gemm3_cp_bf(
    const bf16* __restrict__ A, const bf16* __restrict__ B, bf16* __restrict__ C,
    int N, int K, long sA, long sB, long sC, float alpha, int bDiv)
{
    extern __shared__ char smraw[];
    uint32_t raw  = smem_u32(smraw);
    uint32_t base = (raw + 127u) & ~127u;

    const bf16* Az = A + (long)blockIdx.z * sA;
    const bf16* Bz = B + (long)(blockIdx.z / bDiv) * sB;
    bf16*       Czb = C + (long)blockIdx.z * sC;
    long brow = (long)blockIdx.y * 128;
    long bcol = (long)blockIdx.x * 128;
    int tid  = threadIdx.x;
    int lane = tid & 31;
    int wid  = tid >> 5;
    int wm   = wid & 3;
    int wn   = wid >> 2;

    float acc[2][8][4];
#pragma unroll
    for (int i = 0; i < 2; i++)
#pragma unroll
        for (int j = 0; j < 8; j++)
#pragma unroll
            for (int q = 0; q < 4; q++) acc[i][j][q] = 0.f;

    int NC = K / 64;
    {
        int npre = NC < 2 ? NC : 2;
        for (int s = 0; s < npre; s++) {
            uint32_t st = base + (uint32_t)s * STAGE_BYTES;
            cp_tile(st, st + 16384u, Az, brow, Bz, bcol, s * 64, K, tid);
            asm volatile("cp.async.commit_group;" ::: "memory");
        }
    }

    int aRow = wm * 32 + (lane & 15);
    int aCol = (lane >> 4) * 16;
    int bRow = wn * 64 + ((lane >> 4) << 3) + (lane & 7);
    int bCol = ((lane >> 3) & 1) * 16;

    for (int c = 0; c < NC; c++) {
        if (c + 1 < NC) asm volatile("cp.async.wait_group 1;" ::: "memory");
        else            asm volatile("cp.async.wait_group 0;" ::: "memory");
        __syncthreads();

        if (c + 2 < NC) {
            uint32_t st = base + (uint32_t)((c + 2) % STAGES) * STAGE_BYTES;
            cp_tile(st, st + 16384u, Az, brow, Bz, bcol, (c + 2) * 64, K, tid);
            asm volatile("cp.async.commit_group;" ::: "memory");
        }

        uint32_t smA = base + (uint32_t)(c % STAGES) * STAGE_BYTES;
        uint32_t smB = smA + 16384u;

#pragma unroll
        for (int ks = 0; ks < 4; ks++) {
            uint32_t a[2][4];
#pragma unroll
            for (int mt = 0; mt < 2; mt++) {
                uint32_t bo = (uint32_t)((aRow + mt * 16) * 128 + aCol + ks * 32);
                ldmatrix_x4(a[mt], smA + sw128(bo));
            }
            uint32_t bb[4][4];
#pragma unroll
            for (int p = 0; p < 4; p++) {
                uint32_t bo = (uint32_t)((bRow + p * 16) * 128 + bCol + ks * 32);
                ldmatrix_x4(bb[p], smB + sw128(bo));
            }
#pragma unroll
            for (int mt = 0; mt < 2; mt++)
#pragma unroll
                for (int nt = 0; nt < 8; nt++)
                    mma16816(acc[mt][nt], a[mt], &bb[nt >> 1][(nt & 1) * 2]);
        }
        __syncthreads();
    }

    long r0 = brow + wm * 32 + (lane >> 2);
    long c0 = bcol + wn * 64 + (lane & 3) * 2;
#pragma unroll
    for (int mt = 0; mt < 2; mt++) {
#pragma unroll
        for (int nt = 0; nt < 8; nt++) {
            long rr = r0 + mt * 16;
            long cc = c0 + nt * 8;
            __nv_bfloat162 v0 = __floats2bfloat162_rn(alpha * acc[mt][nt][0], alpha * acc[mt][nt][1]);
            __nv_bfloat162 v1 = __floats2bfloat162_rn(alpha * acc[mt][nt][2], alpha * acc[mt][nt][3]);
            *(__nv_bfloat162*)(Czb + rr * N + cc)       = v0;
            *(__nv_bfloat162*)(Czb + (rr + 8) * N + cc) = v1;
        }
    }
}

// ================= fp32 -> 2-limb elementwise conversion ====================
__global__ void conv2_kernel(const float4* __restrict__ src,
                             uint2* __restrict__ d1, uint2* __restrict__ d2, long n4)
{
    long i = (long)blockIdx.x * blockDim.x + threadIdx.x;
    if (i >= n4) return;
    float4 f = src[i];
    union { bf16 h[4]; uint2 u; } H1, H2;
    float fa[4] = {f.x, f.y, f.z, f.w};
#pragma unroll
    for (int j = 0; j < 4; j++) {
        H1.h[j] = __float2bfloat16(fa[j]);
        H2.h[j] = __float2bfloat16(fa[j] - __bfloat162float(H1.h[j]));
    }
    d1[i] = H1.u;
    d2[i] = H2.u;
}

// ================= rms-norm + rope (fused partial-halves add) ===============
__device__ __forceinline__ float blockSum128(float v, float* red) {
#pragma unroll
    for (int o = 16; o > 0; o >>= 1) v += __shfl_down_sync(0xffffffffu, v, o);
    if ((threadIdx.x & 31) == 0) red[threadIdx.x >> 5] = v;
    __syncthreads();
    return red[0] + red[1] + red[2] + red[3];
}

__global__ void rope_q_kernel(const float* __restrict__ cosb,
                              const float* __restrict__ sinb,
                              const float* __restrict__ w)
{
    int s = blockIdx.x, h = blockIdx.y, d = threadIdx.x;
    __shared__ float red[4];
    __shared__ float sh[HD];
    size_t off = (size_t)s * DM + h * HD + d;
    float v = g_qp[off] + g_qp[(size_t)SQ * DM + off];
    float ss = blockSum128(v * v, red);
    float inv = rsqrtf(ss * (1.0f / HD) + 1e-6f);
    float qn = v * inv * w[d];
    sh[d] = qn;
    __syncthreads();
    float rot = (d < 64) ? -sh[d + 64] : sh[d - 64];
    float f = qn * cosb[s * HD + d] + rot * sinb[s * HD + d];
    g_qr [((size_t)h * SQ + s) * HD + d] = f;
    g_qr1[((size_t)h * SQ + s) * HD + d] = __float2bfloat16(f);
}

__global__ void rope_k_kernel(const float* __restrict__ cosb,
                              const float* __restrict__ sinb,
                              const float* __restrict__ w)
{
    int s = blockIdx.x, h = blockIdx.y, d = threadIdx.x;
    __shared__ float red[4];
    __shared__ float sh[HD];
    size_t off = (size_t)s * KN + h * HD + d;
    float v = g_kp[off] + g_kp[(size_t)SQ * KN + off];
    float ss = blockSum128(v * v, red);
    float inv = rsqrtf(ss * (1.0f / HD) + 1e-6f);
    float kn = v * inv * w[d];
    sh[d] = kn;
    __syncthreads();
    float rot = (d < 64) ? -sh[d + 64] : sh[d - 64];
    float f = kn * cosb[s * HD + d] + rot * sinb[s * HD + d];
    g_kr [((size_t)h * SQ + s) * HD + d] = f;
    g_kr1[((size_t)h * SQ + s) * HD + d] = __float2bfloat16(f);
}

// ================= screening + exact rescore + softmax + sparse PV ==========
__device__ __forceinline__ unsigned fkey(float f) {
    unsigned u = __float_as_uint(f);
    return (u & 0x80000000u) ? ~u : (u | 0x80000000u);
}
__device__ __forceinline__ float unfkey(unsigned u) {
    unsigned v = (u & 0x80000000u) ? (u & 0x7FFFFFFFu) : ~u;
    return __uint_as_float(v);
}

#define CAP 320

__global__ void attn_select_kernel()
{
    int row = blockIdx.x, h = blockIdx.y;
    int kvh = h >> 1;
    int t = threadIdx.x;
    int lane = t & 31;
    int wid  = t >> 5;
    const uint4* srow = (const uint4*)(g_scb + ((size_t)h * SQ + row) * SQ);

    float    val[16];
    unsigned key[16];
#pragma unroll
    for (int i = 0; i < 2; i++) {
        uint4 u = srow[t + i * 128];
        unsigned ws[4] = {u.x, u.y, u.z, u.w};
#pragma unroll
        for (int wq = 0; wq < 4; wq++) {
            float lo = __bfloat162float(__ushort_as_bfloat16((unsigned short)(ws[wq] & 0xFFFFu)));
            float hi = __bfloat162float(__ushort_as_bfloat16((unsigned short)(ws[wq] >> 16)));
            int j = i * 8 + wq * 2;
            val[j] = lo;     key[j]     = fkey(lo);
            val[j + 1] = hi; key[j + 1] = fkey(hi);
        }
    }

    __shared__ float redf[4];
    __shared__ int   redc[2][4];

    unsigned thrKey = 0u;
#pragma unroll
    for (int b = 31; b >= 16; b--) {
        unsigned cand = thrKey | (1u << b);
        int c = 0;
#pragma unroll
        for (int i = 0; i < 16; i++) c += (key[i] >= cand);
        c = __reduce_add_sync(0xffffffffu, c);
        int buf = b & 1;
        if (lane == 0) redc[buf][wid] = c;
        __syncthreads();
        int cnt = redc[buf][0] + redc[buf][1] + redc[buf][2] + redc[buf][3];
        if (cnt >= TOPK) thrKey = cand;
    }
    float thr  = unfkey(thrKey);
    float band = thr - (0.06f + 0.01f * fabsf(thr));

    unsigned mask = 0;
#pragma unroll
    for (int i = 0; i < 16; i++) {
        int col = 8 * (t + (i >> 3) * 128) + (i & 7);
        if (val[i] >= band || col == row) mask |= (1u << i);
    }
    int mc = __popc(mask);

    __shared__ int cnts[129];
    cnts[t] = mc;
    __syncthreads();
    if (t == 0) {
        int a = 0;
        for (int x = 0; x < 128; x++) { int c = cnts[x]; cnts[x] = a; a += c; }
        cnts[128] = a;
    }
    __syncthreads();
    int total = cnts[128];
    if (total > CAP) total = CAP;

    __shared__ int    sIdx[CAP];
    __shared__ float  sEx[CAP];
    __shared__ float  sP[CAP];
    __shared__ float4 sQ4[32];
    {
        int p = cnts[t];
#pragma unroll
        for (int i = 0; i < 16; i++) {
            if (mask & (1u << i)) {
                if (p < CAP) sIdx[p] = 8 * (t + (i >> 3) * 128) + (i & 7);
                p++;
            }
        }
    }
    if (t < 32) sQ4[t] = ((const float4*)(g_qr + ((size_t)h * SQ + row) * HD))[t];
    __syncthreads();

    for (int c = wid; c < total; c += 4) {
        const float4* kp = (const float4*)(g_kr + ((size_t)kvh * SQ + sIdx[c]) * HD);
        float4 k4 = kp[lane];
        float4 q4 = sQ4[lane];
        float part = q4.x * k4.x;
        part = fmaf(q4.y, k4.y, part);
        part = fmaf(q4.z, k4.z, part);
        part = fmaf(q4.w, k4.w, part);
#pragma unroll
        for (int o = 16; o > 0; o >>= 1) part += __shfl_down_sync(0xffffffffu, part, o);
        if (lane == 0) sEx[c] = SCALE * part;
    }
    __syncthreads();

    float m = -3.4e38f;
    for (int c = t; c < total; c += 128) m = fmaxf(m, sEx[c]);
#pragma unroll
    for (int o = 16; o > 0; o >>= 1) m = fmaxf(m, __shfl_down_sync(0xffffffffu, m, o));
    if (lane == 0) redf[wid] = m;
    __syncthreads();
    float rowmax = fmaxf(fmaxf(redf[0], redf[1]), fmaxf(redf[2], redf[3]));

    for (int c = t; c < total; c += 128) {
        float v = sEx[c];
        int cnt = 0;
        for (int c2 = 0; c2 < total; c2++) cnt += (sEx[c2] > v);
        bool kept = (cnt < TOPK) || (sIdx[c] == row);
        sP[c] = kept ? __expf(v - rowmax) : 0.f;
    }
    __syncthreads();

    float ps = 0.f;
    for (int c = t; c < total; c += 128) ps += sP[c];
#pragma unroll
    for (int o = 16; o > 0; o >>= 1) ps += __shfl_down_sync(0xffffffffu, ps, o);
    if (lane == 0) redf[wid] = ps;
    __syncthreads();
    float denom = redf[0] + redf[1] + redf[2] + redf[3];

    float acc = 0.f;
    for (int c = 0; c < total; c++)
        acc += sP[c] * g_v[(size_t)sIdx[c] * KN + kvh * HD + t];

    float o = acc / denom;
    bf16 h1 = __float2bfloat16(o);
    bf16 h2 = __float2bfloat16(o - __bfloat162float(h1));
    int col = h * HD + t;
    g_ath1[(size_t)row * DM + col] = h1;
    g_ath2[(size_t)row * DM + col] = h2;
}

// ================= launch (single stream — linear graph) =====================
extern "C" void kernel_launch(void* const* d_in, const int* in_sizes, int n_in,
                              void* d_out, int out_size)
{
    const float* x    = (const float*)d_in[0];
    const float* cosb = (const float*)d_in[1];
    const float* sinb = (const float*)d_in[2];
    const float* Wq   = (const float*)d_in[3];
    const float* Wk   = (const float*)d_in[4];
    const float* Wv   = (const float*)d_in[5];
    const float* Wo   = (const float*)d_in[6];
    const float* qw   = (const float*)d_in[7];
    const float* kw   = (const float*)d_in[8];
    float* out = (float*)d_out;

    float *pv, *pxT, *pwqT, *pwkT;
    bf16 *pscb, *pxh1, *pxh2, *pwvh1, *pwvh2, *pwoh1, *pwoh2, *path1, *path2, *pqr1, *pkr1;
    cudaGetSymbolAddress((void**)&pv,    g_v);
    cudaGetSymbolAddress((void**)&pxT,   g_xT);
    cudaGetSymbolAddress((void**)&pwqT,  g_wqT);
    cudaGetSymbolAddress((void**)&pwkT,  g_wkT);
    cudaGetSymbolAddress((void**)&pscb,  g_scb);
    cudaGetSymbolAddress((void**)&pxh1,  g_xh1);
    cudaGetSymbolAddress((void**)&pxh2,  g_xh2);
    cudaGetSymbolAddress((void**)&pwvh1, g_wvh1);
    cudaGetSymbolAddress((void**)&pwvh2, g_wvh2);
    cudaGetSymbolAddress((void**)&pwoh1, g_woh1);
    cudaGetSymbolAddress((void**)&pwoh2, g_woh2);
    cudaGetSymbolAddress((void**)&path1, g_ath1);
    cudaGetSymbolAddress((void**)&path2, g_ath2);
    cudaGetSymbolAddress((void**)&pqr1,  g_qr1);
    cudaGetSymbolAddress((void**)&pkr1,  g_kr1);

    static bool attr_done = false;
    if (!attr_done) {
        cudaFuncSetAttribute(gemm3_cp_bf, cudaFuncAttributeMaxDynamicSharedMemorySize, GEMM3_SMEM);
        cudaFuncSetAttribute(gemm2l,      cudaFuncAttributeMaxDynamicSharedMemorySize, GEMM2L_SMEM);
        cudaFuncSetAttribute(qk_gemm,     cudaFuncAttributeMaxDynamicSharedMemorySize, QK_SMEM);
        attr_done = true;
    }

    // transposes for cp.async k-major tiles (x, Wq, Wk)
    transpose_kernel<<<dim3(DM / 32, SQ / 32), dim3(32, 8)>>>(x,  pxT,  SQ, DM);
    transpose_kernel<<<dim3(DM / 32, DM / 32), dim3(32, 8)>>>(Wq, pwqT, DM, DM);
    transpose_kernel<<<dim3(DM / 32, KN / 32), dim3(32, 8)>>>(Wk, pwkT, KN, DM);

    // 2-limb conversions (x, Wv, Wo)
    {
        long n4;
        n4 = (long)SQ * DM / 4;
        conv2_kernel<<<(unsigned)((n4 + 255) / 256), 256>>>((const float4*)x,  (uint2*)pxh1,  (uint2*)pxh2,  n4);
        n4 = (long)KN * DM / 4;
        conv2_kernel<<<(unsigned)((n4 + 255) / 256), 256>>>((const float4*)Wv, (uint2*)pwvh1, (uint2*)pwvh2, n4);
        n4 = (long)DM * DM / 4;
        conv2_kernel<<<(unsigned)((n4 + 255) / 256), 256>>>((const float4*)Wo, (uint2*)pwoh1, (uint2*)pwoh2, n4);
    }

    // fused Q+K fp32 projection (cp.async 3-stage, 16x8 tile, K-split x2)
    qk_gemm<<<dim3(24, 8, 2), 256, QK_SMEM>>>();

    // V projection: 2-limb HMMA (3 passes/chunk)
    gemm2l<<<dim3(KN / 128, SQ / 128), 256, GEMM2L_SMEM>>>(pxh1, pxh2, pwvh1, pwvh2, pv, KN, DM);

    // rms-norm + rope
    rope_q_kernel<<<dim3(SQ, NH),  128>>>(cosb, sinb, qw);
    rope_k_kernel<<<dim3(SQ, NKV), 128>>>(cosb, sinb, kw);

    // screening scores: plain bf16 in/out
    gemm3_cp_bf<<<dim3(SQ / 128, SQ / 128, NH), 256, GEMM3_SMEM>>>(
        pqr1, pkr1, pscb, SQ, HD,
        (long)SQ * HD, (long)SQ * HD, (long)SQ * SQ, SCALE, 2);

    // screening + exact fp32 rescore + softmax + sparse PV (writes at limbs)
    attn_select_kernel<<<dim3(SQ, NH), 128>>>();

    // O projection: 2-limb HMMA
    gemm2l<<<dim3(DM / 128, SQ / 128), 256, GEMM2L_SMEM>>>(path1, path2, pwoh1, pwoh2, out, DM, DM);
}